// round 3
// baseline (speedup 1.0000x reference)
#include <cuda_runtime.h>

// ForceAggregation: out[m*D + r] = dot(hess[m][r][:], ns[m][:]),  D=300, M=2048.
// Pure HBM stream (hess = 737 MB read once).
// One warp = one (molecule, 4-row quad). 300 = 75 quads -> zero tail.
// 12 independent LDG.128.LDCS front-batched per warp (+3 ns loads), MLP~15.
// 9-shuffle interleaved reduction of 4 accumulators.

#define BLOCK_THREADS 256
#define WARPS_PER_BLOCK (BLOCK_THREADS / 32)

__device__ __forceinline__ float dot4(float4 a, float4 b, float acc) {
    acc = fmaf(a.x, b.x, acc);
    acc = fmaf(a.y, b.y, acc);
    acc = fmaf(a.z, b.z, acc);
    return fmaf(a.w, b.w, acc);
}

__global__ void __launch_bounds__(BLOCK_THREADS)
force_agg_300(const float* __restrict__ hess,
              const float* __restrict__ ns,
              float* __restrict__ out)
{
    constexpr int D    = 300;
    constexpr int NCH  = D / 4;        // 75 float4 chunks per row
    constexpr int QPM  = D / 4;        // 75 quads per molecule

    const int wglob = blockIdx.x * WARPS_PER_BLOCK + (threadIdx.x >> 5);
    const int lane  = threadIdx.x & 31;
    const int m     = wglob / QPM;
    const int quad  = wglob - m * QPM;
    const int r     = quad << 2;       // rows r..r+3, always in-range

    const float4 z4 = make_float4(0.f, 0.f, 0.f, 0.f);

    // ns chunks for this lane (reused by all 4 rows)
    const float4* ns4 = (const float4*)(ns + (size_t)m * D);
    float4 n0 = __ldg(ns4 + lane);
    float4 n1 = __ldg(ns4 + lane + 32);
    float4 n2 = (lane < NCH - 64) ? __ldg(ns4 + lane + 64) : z4;

    const float* hbase = hess + (size_t)m * D * D + (size_t)r * D;
    const float4* h0 = (const float4*)(hbase);
    const float4* h1 = (const float4*)(hbase + D);
    const float4* h2 = (const float4*)(hbase + 2 * D);
    const float4* h3 = (const float4*)(hbase + 3 * D);

    // Front-batch 12 independent streaming loads (evict-first).
    float4 a0 = __ldcs(h0 + lane);
    float4 b0 = __ldcs(h1 + lane);
    float4 c0 = __ldcs(h2 + lane);
    float4 d0 = __ldcs(h3 + lane);
    float4 a1 = __ldcs(h0 + lane + 32);
    float4 b1 = __ldcs(h1 + lane + 32);
    float4 c1 = __ldcs(h2 + lane + 32);
    float4 d1 = __ldcs(h3 + lane + 32);
    float4 a2 = z4, b2 = z4, c2 = z4, d2 = z4;
    if (lane < NCH - 64) {
        a2 = __ldcs(h0 + lane + 64);
        b2 = __ldcs(h1 + lane + 64);
        c2 = __ldcs(h2 + lane + 64);
        d2 = __ldcs(h3 + lane + 64);
    }

    float acc0 = dot4(a0, n0, 0.f);
    float acc1 = dot4(b0, n0, 0.f);
    float acc2 = dot4(c0, n0, 0.f);
    float acc3 = dot4(d0, n0, 0.f);
    acc0 = dot4(a1, n1, acc0);
    acc1 = dot4(b1, n1, acc1);
    acc2 = dot4(c1, n1, acc2);
    acc3 = dot4(d1, n1, acc3);
    acc0 = dot4(a2, n2, acc0);
    acc1 = dot4(b2, n2, acc1);
    acc2 = dot4(c2, n2, acc2);
    acc3 = dot4(d2, n2, acc3);

    // Interleaved select-butterfly: 9 shuffles reduce 4 values.
    // Stage 1 (off 16): fold each acc across halves, then select.
    acc0 += __shfl_xor_sync(0xffffffffu, acc0, 16);
    acc1 += __shfl_xor_sync(0xffffffffu, acc1, 16);
    acc2 += __shfl_xor_sync(0xffffffffu, acc2, 16);
    acc3 += __shfl_xor_sync(0xffffffffu, acc3, 16);
    float v0 = (lane & 16) ? acc1 : acc0;   // halves: [0-15]=acc0, [16-31]=acc1
    float v1 = (lane & 16) ? acc3 : acc2;   //         [0-15]=acc2, [16-31]=acc3
    // Stage 2 (off 8): fold within 16-groups, then select.
    v0 += __shfl_xor_sync(0xffffffffu, v0, 8);
    v1 += __shfl_xor_sync(0xffffffffu, v1, 8);
    float w = (lane & 8) ? v1 : v0;
    // 8-groups now hold: [0-7]=acc0, [8-15]=acc2, [16-23]=acc1, [24-31]=acc3
    w += __shfl_xor_sync(0xffffffffu, w, 4);
    w += __shfl_xor_sync(0xffffffffu, w, 2);
    w += __shfl_xor_sync(0xffffffffu, w, 1);

    if ((lane & 7) == 0) {
        // lane 0 -> row r, lane 8 -> r+2, lane 16 -> r+1, lane 24 -> r+3
        const int rowoff = (((lane >> 3) & 1) << 1) | (lane >> 4);
        out[(size_t)m * D + r + rowoff] = w;
    }
}

// Generic fallback for unexpected D (runtime loop bounds, smem-staged ns).
__global__ void __launch_bounds__(BLOCK_THREADS)
force_agg_generic(const float* __restrict__ hess,
                  const float* __restrict__ ns,
                  float* __restrict__ out,
                  int D, int tiles_per_mol)
{
    extern __shared__ __align__(16) float s_ns[];

    const int m    = blockIdx.x / tiles_per_mol;
    const int tile = blockIdx.x - m * tiles_per_mol;
    const int row0 = tile * 64;

    const float* nsm = ns + (size_t)m * D;
    const int nch = D >> 2;
    for (int i = threadIdx.x; i < nch; i += BLOCK_THREADS)
        ((float4*)s_ns)[i] = ((const float4*)nsm)[i];
    for (int i = nch * 4 + threadIdx.x; i < D; i += BLOCK_THREADS)
        s_ns[i] = nsm[i];
    __syncthreads();

    const int warp  = threadIdx.x >> 5;
    const int lane  = threadIdx.x & 31;
    const int nwrps = BLOCK_THREADS >> 5;

    const float4* s4    = (const float4*)s_ns;
    const float*  hbase = hess + (size_t)m * D * D;

    int rend = row0 + 64;
    if (rend > D) rend = D;

    for (int r = row0 + warp; r < rend; r += nwrps) {
        const float4* hrow = (const float4*)(hbase + (size_t)r * D);
        float acc = 0.0f;
        for (int c = lane; c < nch; c += 32) {
            const float4 h = __ldcs(hrow + c);
            const float4 n = s4[c];
            acc = fmaf(h.x, n.x, acc);
            acc = fmaf(h.y, n.y, acc);
            acc = fmaf(h.z, n.z, acc);
            acc = fmaf(h.w, n.w, acc);
        }
        for (int c = nch * 4 + lane; c < D; c += 32)
            acc = fmaf(hbase[(size_t)r * D + c], s_ns[c], acc);
#pragma unroll
        for (int off = 16; off; off >>= 1)
            acc += __shfl_xor_sync(0xffffffffu, acc, off);
        if (lane == 0)
            out[(size_t)m * D + r] = acc;
    }
}

extern "C" void kernel_launch(void* const* d_in, const int* in_sizes, int n_in,
                              void* d_out, int out_size)
{
    // Input order: ns [M*N_AT,3] f32, hess [M*D,D] f32, idx_m i32, n_atoms [M] i32
    const float* ns   = (const float*)d_in[0];
    const float* hess = (const float*)d_in[1];
    float*       out  = (float*)d_out;

    const int M = in_sizes[3];
    const int D = (int)((long long)in_sizes[0] / M);

    if (D == 300) {
        const int total_warps = M * (300 / 4);                 // 153600
        const int blocks = total_warps / WARPS_PER_BLOCK;      // 19200
        force_agg_300<<<blocks, BLOCK_THREADS>>>(hess, ns, out);
    } else {
        const int tiles = (D + 63) / 64;
        const size_t shmem = (size_t)((D + 3) / 4) * 16;
        force_agg_generic<<<(unsigned)(M * tiles), BLOCK_THREADS, shmem>>>(hess, ns, out, D, tiles);
    }
}